// round 16
// baseline (speedup 1.0000x reference)
#include <cuda_runtime.h>
#include <cuda_fp16.h>
#include <cstdint>

#define NROW 16384

// Scratch (allocation-free: __device__ globals)
__device__ __align__(16) float  g_C  [3 * 64 * 64];       // B @ Ws^T @ B^T (atomic-accumulated)
__device__ __align__(16) __half g_DfH[3 * 16 * 4096];     // D fp16 B-image per 64-chunk
__device__ __align__(16) __half g_AfH[3 * 16 * 4096];     // A fp16 B-image per etile
__device__ __align__(16) __half g_UfH[3 * 512 * 2048];    // u fp16 A-image per (kh, 32-row tile)

__device__ __forceinline__ uint32_t smem_u32(const void* p) {
    uint32_t a;
    asm("{ .reg .u64 t; cvta.to.shared.u64 t, %1; cvt.u32.u64 %0, t; }" : "=r"(a) : "l"(p));
    return a;
}

// pack two floats -> f16x2 (lo = first arg)
__device__ __forceinline__ uint32_t pack2h(float lo, float hi) {
    uint32_t r;
    asm("cvt.rn.f16x2.f32 %0, %1, %2;" : "=r"(r) : "f"(hi), "f"(lo));
    return r;
}

// fp16 mma m16n8k16, fp32 accum
__device__ __forceinline__ void mma16(float c[4], const uint32_t a[4], const uint32_t b[2]) {
    asm volatile(
        "mma.sync.aligned.m16n8k16.row.col.f32.f16.f16.f32 "
        "{%0,%1,%2,%3},{%4,%5,%6,%7},{%8,%9},{%0,%1,%2,%3};"
        : "+f"(c[0]), "+f"(c[1]), "+f"(c[2]), "+f"(c[3])
        : "r"(a[0]), "r"(a[1]), "r"(a[2]), "r"(a[3]), "r"(b[0]), "r"(b[1]));
}

#define CP_ASYNC16(dst, src) \
    asm volatile("cp.async.cg.shared.global [%0], [%1], 16;" :: "r"(dst), "l"(src) : "memory")
#define CP_COMMIT() asm volatile("cp.async.commit_group;" ::: "memory")
#define CP_WAIT0()  asm volatile("cp.async.wait_group 0;" ::: "memory")

// A-image lane swizzle: f(ks4) in {0,1,4,5}
__device__ __forceinline__ int fsw(int ks4) { return (ks4 & 1) | ((ks4 & 2) << 1); }

// B-image half position for element (n-row nr, k-col kc) in a 64x64 fp16 tile
__device__ __forceinline__ int bhpos(int nr, int kc) {
    int ct = nr >> 3, ln = (nr & 7) * 4 + ((kc & 7) >> 1);
    int ks4 = kc >> 4, q = (kc >> 3) & 1, hb = kc & 1;
    return (ct * 4 + ks4) * 128 + ln * 4 + q * 2 + hb;
}

// ---------------- precompute ----------------

__global__ void zero_k() {
    int i = blockIdx.x * blockDim.x + threadIdx.x;
    if (i < 3 * 64 * 64) g_C[i] = 0.f;
}

// Fused T1+C (+ A-image build folded into spare grid slots).
// grid (9, 12, 3), block 256, dynamic smem 69632B:
//   x < 6 : T1+C partial for (s-block x, t-split y of 64, k=z)
//   x >= 6: A-image build unit xb = (x-6)*12 + y (if xb < 32), k=z
__global__ __launch_bounds__(256) void t1c_k(const float* __restrict__ B,
                                             const float* __restrict__ Ws,
                                             const float* __restrict__ A) {
    int k = blockIdx.z;
    int tid = threadIdx.x;

    if (blockIdx.x >= 6) {
        int xb = (blockIdx.x - 6) * 12 + blockIdx.y;
        if (xb >= 32) return;
        int s = xb * 256 + tid;            // 0..8191
        int et = s >> 9;
        int wslot = s & 511;
        int j   = wslot & 15;
        int ks4 = (wslot >> 4) & 3;
        int ct  = wslot >> 6;
        const float* Ae = A + (size_t)(k * 1024 + et * 64) * 64;
        uint32_t w4[4];
#pragma unroll
        for (int lp = 0; lp < 2; lp++) {
            int ln = 2 * j + lp;
            int nr = ct * 8 + (ln >> 2);
            int kb = ks4 * 16 + (ln & 3) * 2;
#pragma unroll
            for (int q = 0; q < 2; q++) {
                float lo = Ae[nr * 64 + kb + q * 8];
                float hi = Ae[nr * 64 + kb + q * 8 + 1];
                w4[lp * 2 + q] = pack2h(lo, hi);
            }
        }
        int wbase = ((ct * 4 + ks4) * 128 + 2 * j * 4) >> 1;
        *(uint4*)&((uint32_t*)g_AfH)[((size_t)k * 16 + et) * 2048 + wbase] =
            make_uint4(w4[0], w4[1], w4[2], w4[3]);
        return;
    }

    extern __shared__ float sm[];
    float* Tloc = sm;                       // 64 x 133
    float* BsA  = sm + 64 * 133;            // phase A: 64 x 33
    float* WssA = sm + 64 * 133 + 64 * 33;  // phase A: 128 x 33
    float* Btile = sm + 64 * 133;           // phase B: 64 x 133

    int s0 = blockIdx.x * 128, t0 = blockIdx.y * 64;
    const float* Bk = B  + k * 64 * 768;
    const float* Wk = Ws + k * 768 * 768;

    float acc[4][8];
#pragma unroll
    for (int i = 0; i < 4; i++)
#pragma unroll
        for (int j = 0; j < 8; j++) acc[i][j] = 0.f;

    int rl = tid >> 4;
    int sl = tid & 15;

    for (int tc = 0; tc < 64; tc += 32) {
        int tb = t0 + tc;
        int c4 = (tid & 7) * 4;
#pragma unroll
        for (int pp = 0; pp < 2; pp++) {
            int r = (tid >> 3) + pp * 32;
            float4 v = *(const float4*)(Bk + r * 768 + tb + c4);
            BsA[r * 33 + c4] = v.x; BsA[r * 33 + c4 + 1] = v.y;
            BsA[r * 33 + c4 + 2] = v.z; BsA[r * 33 + c4 + 3] = v.w;
        }
#pragma unroll
        for (int pp = 0; pp < 4; pp++) {
            int s = (tid >> 3) + pp * 32;
            float4 v = *(const float4*)(Wk + (s0 + s) * 768 + tb + c4);
            WssA[s * 33 + c4] = v.x; WssA[s * 33 + c4 + 1] = v.y;
            WssA[s * 33 + c4 + 2] = v.z; WssA[s * 33 + c4 + 3] = v.w;
        }
        __syncthreads();
#pragma unroll 8
        for (int tt = 0; tt < 32; tt++) {
            float bv[4], wv[8];
#pragma unroll
            for (int i = 0; i < 4; i++) bv[i] = BsA[(rl + 16 * i) * 33 + tt];
#pragma unroll
            for (int j = 0; j < 8; j++) wv[j] = WssA[(sl + 16 * j) * 33 + tt];
#pragma unroll
            for (int i = 0; i < 4; i++)
#pragma unroll
                for (int j = 0; j < 8; j++) acc[i][j] += bv[i] * wv[j];
        }
        __syncthreads();
    }

#pragma unroll
    for (int i = 0; i < 4; i++)
#pragma unroll
        for (int j = 0; j < 8; j++)
            Tloc[(rl + 16 * i) * 133 + sl + 16 * j] = acc[i][j];
    __syncthreads();

    for (int idx = tid; idx < 2048; idx += 256) {
        int row = idx >> 5, c4 = (idx & 31) * 4;
        float4 v = *(const float4*)(Bk + row * 768 + s0 + c4);
        Btile[row * 133 + c4] = v.x; Btile[row * 133 + c4 + 1] = v.y;
        Btile[row * 133 + c4 + 2] = v.z; Btile[row * 133 + c4 + 3] = v.w;
    }
    __syncthreads();

    float c2[4][4];
#pragma unroll
    for (int i = 0; i < 4; i++)
#pragma unroll
        for (int j = 0; j < 4; j++) c2[i][j] = 0.f;

    int rl2 = tid & 15;
    int r2l = tid >> 4;
#pragma unroll 4
    for (int s = 0; s < 128; s++) {
        float tv[4], bv[4];
#pragma unroll
        for (int i = 0; i < 4; i++) tv[i] = Tloc[(rl2 + 16 * i) * 133 + s];
#pragma unroll
        for (int j = 0; j < 4; j++) bv[j] = Btile[(r2l + 16 * j) * 133 + s];
#pragma unroll
        for (int i = 0; i < 4; i++)
#pragma unroll
            for (int j = 0; j < 4; j++) c2[i][j] += tv[i] * bv[j];
    }
#pragma unroll
    for (int i = 0; i < 4; i++)
#pragma unroll
        for (int j = 0; j < 4; j++)
            atomicAdd(&g_C[k * 4096 + (rl2 + 16 * i) * 64 + r2l + 16 * j], c2[i][j]);
}

// D-part only: D[k][d][r] -> g_DfH fp16 B-image. grid (128, 3), block 256.
__global__ __launch_bounds__(256) void d_k(const float* __restrict__ A) {
    int k = blockIdx.y;
    __shared__ float Cs[64][66];
    __shared__ float As[8][64];
    int d0 = blockIdx.x * 8;
    int tid = threadIdx.x;
    for (int idx = tid; idx < 4096; idx += 256)
        Cs[idx >> 6][idx & 63] = g_C[k * 4096 + idx];
    for (int idx = tid; idx < 512; idx += 256)
        As[idx >> 6][idx & 63] = A[(size_t)(k * 1024 + d0 + (idx >> 6)) * 64 + (idx & 63)];
    __syncthreads();
    int dl = tid >> 5, r = (tid & 31) * 2;
    float a0 = 0.f, a1 = 0.f;
#pragma unroll
    for (int rp = 0; rp < 64; rp++) {
        float av = As[dl][rp];
        float2 c = *(const float2*)&Cs[rp][r];
        a0 += av * c.x; a1 += av * c.y;
    }
    int d = d0 + dl;
    __half* img = g_DfH + ((size_t)k * 16 + (d >> 6)) * 4096;
    int rr = d & 63;
    img[bhpos(r, rr)]     = __float2half(a0);
    img[bhpos(r + 1, rr)] = __float2half(a1);
}

// ---------------- s1: u[32,192] = x_tile @ [D0|D1|D2] (kh-merged) ----------------
// grid (512), block 128 (4 warps, each = 32 rows x 48 cols, nt=6 across 3 kh images).
// dynamic smem 52KB: sA 4KB (x A-image, 32 rows) + sB 2 x 24KB (3 kh D images).
__global__ __launch_bounds__(128, 4) void s1_k(const float* __restrict__ x) {
    extern __shared__ uint32_t sd1[];
    uint32_t* const sA = sd1;                    // 1024 words
    uint32_t* const sBb[2] = {sd1 + 1024, sd1 + 1024 + 6144};
    const uint32_t sBa[2] = {smem_u32(sBb[0]), smem_u32(sBb[1])};

    const int tid = threadIdx.x;
    const int w = tid >> 5, lane = tid & 31;
    const int yt = blockIdx.x;
    const int r0 = yt * 32;

    const int g = tid >> 4;
    const int m = tid & 15;
    const int c4 = m * 4;
    const int ks4X = m >> 2, cphiX = (m >> 1) & 1, fX = fsw(ks4X);
    const int tg0 = (m & 1) * 2;

    uint2 xh[4];
#pragma unroll
    for (int rt = 0; rt < 2; rt++)
#pragma unroll
        for (int h = 0; h < 2; h++) {
            float4 v = *(const float4*)(x + (size_t)(r0 + rt * 16 + h * 8 + g) * 1024 + c4);
            xh[rt * 2 + h] = make_uint2(pack2h(v.x, v.y), pack2h(v.z, v.w));
        }
#pragma unroll
    for (int p = 0; p < 12; p++) {
        int kh = p >> 2, q = p & 3;
        const char* src = (const char*)(g_DfH + (size_t)kh * 16 * 4096) + (tid + q * 128) * 16;
        CP_ASYNC16(sBa[0] + kh * 8192 + (tid + q * 128) * 16, src);
    }
    CP_COMMIT();

    float acc[2][6][4];
#pragma unroll
    for (int mt = 0; mt < 2; mt++)
#pragma unroll
        for (int nt = 0; nt < 6; nt++)
#pragma unroll
            for (int i = 0; i < 4; i++) acc[mt][nt][i] = 0.f;

    for (int ci = 0; ci < 16; ci++) {
        const int b = ci & 1;
#pragma unroll
        for (int rt = 0; rt < 2; rt++) {
            uint2 h0 = xh[rt * 2], h1 = xh[rt * 2 + 1];
#pragma unroll
            for (int cs = 0; cs < 2; cs++) {
                int tg = tg0 + cs;
                int lane2 = (g * 4 + tg) ^ fX;
                int word = ((rt * 4 + ks4X) * 32 + lane2) * 4 + cphiX * 2;
                uint32_t lo = cs ? h0.y : h0.x;
                uint32_t hi = cs ? h1.y : h1.x;
                asm volatile("st.shared.v2.b32 [%0], {%1,%2};"
                             :: "r"(smem_u32(&sA[word])), "r"(lo), "r"(hi) : "memory");
            }
        }
        CP_WAIT0();
        __syncthreads();

        if (ci < 15) {
            int kc = (ci + 1) * 64;
#pragma unroll
            for (int rt = 0; rt < 2; rt++)
#pragma unroll
                for (int h = 0; h < 2; h++) {
                    float4 v = *(const float4*)(x + (size_t)(r0 + rt * 16 + h * 8 + g) * 1024 + kc + c4);
                    xh[rt * 2 + h] = make_uint2(pack2h(v.x, v.y), pack2h(v.z, v.w));
                }
            const uint32_t dst = sBa[1 - b];
#pragma unroll
            for (int p = 0; p < 12; p++) {
                int kh = p >> 2, q = p & 3;
                const char* src = (const char*)(g_DfH + (size_t)kh * 16 * 4096)
                                  + (size_t)(ci + 1) * 8192 + (tid + q * 128) * 16;
                CP_ASYNC16(dst + kh * 8192 + (tid + q * 128) * 16, src);
            }
            CP_COMMIT();
        }

        const uint32_t* Bp = sBb[b];
#pragma unroll
        for (int ks4 = 0; ks4 < 4; ks4++) {
            int lsw = lane ^ fsw(ks4);
            uint32_t a0[4], a1[4];
            *(uint4*)a0 = *(const uint4*)&sA[((0 * 4 + ks4) * 32 + lsw) * 4];
            *(uint4*)a1 = *(const uint4*)&sA[((1 * 4 + ks4) * 32 + lsw) * 4];
#pragma unroll
            for (int nt = 0; nt < 6; nt++) {
                int n = w * 48 + nt * 8;
                int kh = n >> 6, ct = (n >> 3) & 7;
                uint32_t bb[2];
                *(uint2*)bb = *(const uint2*)&Bp[kh * 2048 + ((ct * 4 + ks4) * 32 + lane) * 2];
                mma16(acc[0][nt], a0, bb);
                mma16(acc[1][nt], a1, bb);
            }
        }
        __syncthreads();
    }

#pragma unroll
    for (int mt = 0; mt < 2; mt++) {
#pragma unroll
        for (int nt = 0; nt < 6; nt++) {
            int n = w * 48 + nt * 8;
            int kh = n >> 6, r = n & 63;
            int ks4u = r >> 4, cphi = (r >> 3) & 1;
            int lane2 = lane ^ fsw(ks4u);
            int word = ((mt * 4 + ks4u) * 32 + lane2) * 4 + cphi * 2;
            uint32_t* Ut = (uint32_t*)g_UfH + ((size_t)kh * 512 + yt) * 1024;
            *(uint2*)&Ut[word] = make_uint2(pack2h(acc[mt][nt][0], acc[mt][nt][1]),
                                            pack2h(acc[mt][nt][2], acc[mt][nt][3]));
        }
    }
}

// ---------------- s2: out = u @ A^T ----------------
// block 128 (4 warps, 2x2), grid (3, 256); 2 etiles per buffer -> 8 iterations.
// smem: sU 8KB (two 32-row u tiles) + sB 2x16KB = 40KB; 5 blocks/SM.
__global__ __launch_bounds__(128, 5) void s2_k(float* __restrict__ out) {
    __shared__ uint32_t sU[2048];        // [tile 0 | tile 1], 1024 words each
    __shared__ uint32_t sB[2][4096];     // 2 x 16KB (2 etiles each)

    const int tid = threadIdx.x;
    const int w = tid >> 5, lane = tid & 31;
    const int gp = lane >> 2, tgp = lane & 3;
    const int kh = blockIdx.x;
    const int r0 = blockIdx.y * 64;
    const int wn = w & 1;
    const int wr = (w >> 1) * 32, wc = wn * 32;
    const int tile = w >> 1;

    const char* Af = (const char*)(g_AfH + (size_t)kh * 16 * 4096);
    const char* Uf = (const char*)((uint32_t*)g_UfH + ((size_t)kh * 512 + blockIdx.y * 2) * 1024);

    const uint32_t sUa = smem_u32(sU);
    const uint32_t sBa[2] = {smem_u32(&sB[0][0]), smem_u32(&sB[1][0])};

    // prologue: both u tiles (8KB) + etile pair 0
#pragma unroll
    for (int p = 0; p < 4; p++)
        CP_ASYNC16(sUa + (tid + p * 128) * 16, Uf + (tid + p * 128) * 16);
#pragma unroll
    for (int p = 0; p < 8; p++)
        CP_ASYNC16(sBa[0] + (tid + p * 128) * 16, Af + (tid + p * 128) * 16);
    CP_COMMIT();
    CP_WAIT0();
    __syncthreads();

    // u-fragments into registers (warp's rows live in tile = w>>1, local rt = mt)
    uint32_t uf[2][4][4];
#pragma unroll
    for (int ks4 = 0; ks4 < 4; ks4++) {
        int lsw = lane ^ fsw(ks4);
        *(uint4*)uf[0][ks4] = *(const uint4*)&sU[tile * 1024 + ((0 * 4 + ks4) * 32 + lsw) * 4];
        *(uint4*)uf[1][ks4] = *(const uint4*)&sU[tile * 1024 + ((1 * 4 + ks4) * 32 + lsw) * 4];
    }

    for (int it = 0; it < 8; it++) {
        const int b = it & 1;
        if (it > 0) {
            CP_WAIT0();
            __syncthreads();
        }
        if (it < 7) {
            const char* srcA = Af + (size_t)(it + 1) * 16384;
#pragma unroll
            for (int p = 0; p < 8; p++)
                CP_ASYNC16(sBa[1 - b] + (tid + p * 128) * 16, srcA + (tid + p * 128) * 16);
            CP_COMMIT();
        }

#pragma unroll
        for (int sub = 0; sub < 2; sub++) {
            int et = 2 * it + sub;
            const uint32_t* Bp = &sB[b][sub * 2048];

            float o[2][4][4];
#pragma unroll
            for (int mt = 0; mt < 2; mt++)
#pragma unroll
                for (int nt = 0; nt < 4; nt++)
#pragma unroll
                    for (int i = 0; i < 4; i++) o[mt][nt][i] = 0.f;

#pragma unroll
            for (int ks4 = 0; ks4 < 4; ks4++) {
#pragma unroll
                for (int nt = 0; nt < 4; nt++) {
                    uint32_t bb[2];
                    *(uint2*)bb = *(const uint2*)&Bp[(((wn * 4 + nt) * 4 + ks4) * 32 + lane) * 2];
                    mma16(o[0][nt], uf[0][ks4], bb);
                    mma16(o[1][nt], uf[1][ks4], bb);
                }
            }

#pragma unroll
            for (int mt = 0; mt < 2; mt++) {
                int row = r0 + wr + mt * 16 + gp;
#pragma unroll
                for (int nt = 0; nt < 4; nt++) {
                    size_t col = (size_t)kh * 1024 + et * 64 + wc + nt * 8 + 2 * tgp;
                    *(float2*)(out + (size_t)row * 3072 + col) =
                        make_float2(o[mt][nt][0], o[mt][nt][1]);
                    *(float2*)(out + (size_t)(row + 8) * 3072 + col) =
                        make_float2(o[mt][nt][2], o[mt][nt][3]);
                }
            }
        }
    }
}

extern "C" void kernel_launch(void* const* d_in, const int* in_sizes, int n_in,
                              void* d_out, int out_size) {
    (void)in_sizes; (void)n_in; (void)out_size;
    const float* x  = (const float*)d_in[0];
    const float* Ws = (const float*)d_in[1];
    const float* A  = (const float*)d_in[2];
    const float* B  = (const float*)d_in[3];
    float* out = (float*)d_out;

    cudaFuncSetAttribute(t1c_k, cudaFuncAttributeMaxDynamicSharedMemorySize, 69632);
    cudaFuncSetAttribute(s1_k, cudaFuncAttributeMaxDynamicSharedMemorySize, 53248);

    // s1_k is the 4th launch (ncu profiles launch #4)
    zero_k<<<48, 256>>>();
    t1c_k<<<dim3(9, 12, 3), 256, 69632>>>(B, Ws, A);
    d_k<<<dim3(128, 3), 256>>>(A);
    s1_k<<<512, 128, 53248>>>(x);
    s2_k<<<dim3(3, 256), 128>>>(out);
}

// round 17
// speedup vs baseline: 1.1636x; 1.1636x over previous
#include <cuda_runtime.h>
#include <cuda_fp16.h>
#include <cstdint>

#define NROW 16384

// Scratch (allocation-free: __device__ globals)
__device__ __align__(16) float  g_C  [3 * 64 * 64];       // B @ Ws^T @ B^T (atomic-accumulated)
__device__ __align__(16) __half g_DfH[3 * 16 * 4096];     // D fp16 B-image per 64-chunk
__device__ __align__(16) __half g_AfH[3 * 16 * 4096];     // A fp16 B-image per etile

__device__ __forceinline__ uint32_t smem_u32(const void* p) {
    uint32_t a;
    asm("{ .reg .u64 t; cvta.to.shared.u64 t, %1; cvt.u32.u64 %0, t; }" : "=r"(a) : "l"(p));
    return a;
}

// pack two floats -> f16x2 (lo = first arg)
__device__ __forceinline__ uint32_t pack2h(float lo, float hi) {
    uint32_t r;
    asm("cvt.rn.f16x2.f32 %0, %1, %2;" : "=r"(r) : "f"(hi), "f"(lo));
    return r;
}

// fp16 mma m16n8k16, fp32 accum
__device__ __forceinline__ void mma16(float c[4], const uint32_t a[4], const uint32_t b[2]) {
    asm volatile(
        "mma.sync.aligned.m16n8k16.row.col.f32.f16.f16.f32 "
        "{%0,%1,%2,%3},{%4,%5,%6,%7},{%8,%9},{%0,%1,%2,%3};"
        : "+f"(c[0]), "+f"(c[1]), "+f"(c[2]), "+f"(c[3])
        : "r"(a[0]), "r"(a[1]), "r"(a[2]), "r"(a[3]), "r"(b[0]), "r"(b[1]));
}

#define CP_ASYNC16(dst, src) \
    asm volatile("cp.async.cg.shared.global [%0], [%1], 16;" :: "r"(dst), "l"(src) : "memory")
#define CP_COMMIT() asm volatile("cp.async.commit_group;" ::: "memory")
#define CP_WAIT0()  asm volatile("cp.async.wait_group 0;" ::: "memory")

// A-image lane swizzle: f(ks4) in {0,1,4,5}
__device__ __forceinline__ int fsw(int ks4) { return (ks4 & 1) | ((ks4 & 2) << 1); }

// B-image half position for element (n-row nr, k-col kc) in a 64x64 fp16 tile
__device__ __forceinline__ int bhpos(int nr, int kc) {
    int ct = nr >> 3, ln = (nr & 7) * 4 + ((kc & 7) >> 1);
    int ks4 = kc >> 4, q = (kc >> 3) & 1, hb = kc & 1;
    return (ct * 4 + ks4) * 128 + ln * 4 + q * 2 + hb;
}

// ---------------- precompute ----------------

__global__ void zero_k() {
    int i = blockIdx.x * blockDim.x + threadIdx.x;
    if (i < 3 * 64 * 64) g_C[i] = 0.f;
}

// Fused T1+C: per (s-split of 128, t-split of 96, k) block.
// grid (6, 8, 3), block 256, dynamic smem 69632B.
__global__ __launch_bounds__(256) void t1c_k(const float* __restrict__ B,
                                             const float* __restrict__ Ws) {
    extern __shared__ float sm[];
    float* Tloc = sm;                       // 64 x 133
    float* BsA  = sm + 64 * 133;            // phase A: 64 x 33
    float* WssA = sm + 64 * 133 + 64 * 33;  // phase A: 128 x 33
    float* Btile = sm + 64 * 133;           // phase B: 64 x 133

    int k = blockIdx.z, s0 = blockIdx.x * 128, t0 = blockIdx.y * 96;
    int tid = threadIdx.x;
    const float* Bk = B  + k * 64 * 768;
    const float* Wk = Ws + k * 768 * 768;

    float acc[4][8];
#pragma unroll
    for (int i = 0; i < 4; i++)
#pragma unroll
        for (int j = 0; j < 8; j++) acc[i][j] = 0.f;

    int rl = tid >> 4;
    int sl = tid & 15;

    for (int tc = 0; tc < 96; tc += 32) {
        int tb = t0 + tc;
        int c4 = (tid & 7) * 4;
#pragma unroll
        for (int pp = 0; pp < 2; pp++) {
            int r = (tid >> 3) + pp * 32;
            float4 v = *(const float4*)(Bk + r * 768 + tb + c4);
            BsA[r * 33 + c4] = v.x; BsA[r * 33 + c4 + 1] = v.y;
            BsA[r * 33 + c4 + 2] = v.z; BsA[r * 33 + c4 + 3] = v.w;
        }
#pragma unroll
        for (int pp = 0; pp < 4; pp++) {
            int s = (tid >> 3) + pp * 32;
            float4 v = *(const float4*)(Wk + (s0 + s) * 768 + tb + c4);
            WssA[s * 33 + c4] = v.x; WssA[s * 33 + c4 + 1] = v.y;
            WssA[s * 33 + c4 + 2] = v.z; WssA[s * 33 + c4 + 3] = v.w;
        }
        __syncthreads();
#pragma unroll 8
        for (int tt = 0; tt < 32; tt++) {
            float bv[4], wv[8];
#pragma unroll
            for (int i = 0; i < 4; i++) bv[i] = BsA[(rl + 16 * i) * 33 + tt];
#pragma unroll
            for (int j = 0; j < 8; j++) wv[j] = WssA[(sl + 16 * j) * 33 + tt];
#pragma unroll
            for (int i = 0; i < 4; i++)
#pragma unroll
                for (int j = 0; j < 8; j++) acc[i][j] += bv[i] * wv[j];
        }
        __syncthreads();
    }

#pragma unroll
    for (int i = 0; i < 4; i++)
#pragma unroll
        for (int j = 0; j < 8; j++)
            Tloc[(rl + 16 * i) * 133 + sl + 16 * j] = acc[i][j];
    __syncthreads();

    for (int idx = tid; idx < 2048; idx += 256) {
        int row = idx >> 5, c4 = (idx & 31) * 4;
        float4 v = *(const float4*)(Bk + row * 768 + s0 + c4);
        Btile[row * 133 + c4] = v.x; Btile[row * 133 + c4 + 1] = v.y;
        Btile[row * 133 + c4 + 2] = v.z; Btile[row * 133 + c4 + 3] = v.w;
    }
    __syncthreads();

    float c2[4][4];
#pragma unroll
    for (int i = 0; i < 4; i++)
#pragma unroll
        for (int j = 0; j < 4; j++) c2[i][j] = 0.f;

    int rl2 = tid & 15;
    int r2l = tid >> 4;
#pragma unroll 4
    for (int s = 0; s < 128; s++) {
        float tv[4], bv[4];
#pragma unroll
        for (int i = 0; i < 4; i++) tv[i] = Tloc[(rl2 + 16 * i) * 133 + s];
#pragma unroll
        for (int j = 0; j < 4; j++) bv[j] = Btile[(r2l + 16 * j) * 133 + s];
#pragma unroll
        for (int i = 0; i < 4; i++)
#pragma unroll
            for (int j = 0; j < 4; j++) c2[i][j] += tv[i] * bv[j];
    }
#pragma unroll
    for (int i = 0; i < 4; i++)
#pragma unroll
        for (int j = 0; j < 4; j++)
            atomicAdd(&g_C[k * 4096 + (rl2 + 16 * i) * 64 + r2l + 16 * j], c2[i][j]);
}

// Combined, grid (160, 3), block 256:
//  x < 128:  D[k][d][r] -> g_DfH fp16 B-image
//  x >= 128: gather-build g_AfH fp16 B-image from A
__global__ __launch_bounds__(256) void d_k(const float* __restrict__ A) {
    int k = blockIdx.y;
    if (blockIdx.x >= 128) {
        int s = (blockIdx.x - 128) * 256 + threadIdx.x;
        int et = s >> 9;
        int wslot = s & 511;
        int j   = wslot & 15;
        int ks4 = (wslot >> 4) & 3;
        int ct  = wslot >> 6;
        const float* Ae = A + (size_t)(k * 1024 + et * 64) * 64;
        uint32_t w4[4];
#pragma unroll
        for (int lp = 0; lp < 2; lp++) {
            int ln = 2 * j + lp;
            int nr = ct * 8 + (ln >> 2);
            int kb = ks4 * 16 + (ln & 3) * 2;
#pragma unroll
            for (int q = 0; q < 2; q++) {
                float lo = Ae[nr * 64 + kb + q * 8];
                float hi = Ae[nr * 64 + kb + q * 8 + 1];
                w4[lp * 2 + q] = pack2h(lo, hi);
            }
        }
        int wbase = ((ct * 4 + ks4) * 128 + 2 * j * 4) >> 1;
        *(uint4*)&((uint32_t*)g_AfH)[((size_t)k * 16 + et) * 2048 + wbase] =
            make_uint4(w4[0], w4[1], w4[2], w4[3]);
        return;
    }

    __shared__ float Cs[64][66];
    __shared__ float As[8][64];
    int d0 = blockIdx.x * 8;
    int tid = threadIdx.x;
    for (int idx = tid; idx < 4096; idx += 256)
        Cs[idx >> 6][idx & 63] = g_C[k * 4096 + idx];
    for (int idx = tid; idx < 512; idx += 256)
        As[idx >> 6][idx & 63] = A[(size_t)(k * 1024 + d0 + (idx >> 6)) * 64 + (idx & 63)];
    __syncthreads();
    int dl = tid >> 5, r = (tid & 31) * 2;
    float a0 = 0.f, a1 = 0.f;
#pragma unroll
    for (int rp = 0; rp < 64; rp++) {
        float av = As[dl][rp];
        float2 c = *(const float2*)&Cs[rp][r];
        a0 += av * c.x; a1 += av * c.y;
    }
    int d = d0 + dl;
    __half* img = g_DfH + ((size_t)k * 16 + (d >> 6)) * 4096;
    int rr = d & 63;
    img[bhpos(r, rr)]     = __float2half(a0);
    img[bhpos(r + 1, rr)] = __float2half(a1);
}

// ---------------- fused main GEMM (fp16 mma m16n8k16, fp32 accum) ----------------
// Phase 1: u[64,64] = x_tile @ D(kh). Phase 2: out = u @ A(kh)^T over 16 etiles,
// u-frags in registers. block 128 (4 warps, 2x2 of 32x32), grid (3, 256), 24KB smem.
__global__ __launch_bounds__(128, 4) void fused_k(const float* __restrict__ x,
                                                  float* __restrict__ out) {
    __shared__ uint32_t sA[4 * 4 * 32 * 4];      // 8KB: x-frags (A-image), then u-frags
    __shared__ uint32_t sB[2][8 * 4 * 32 * 2];   // 2 x 8KB: D / A fp16 B-images

    const int tid = threadIdx.x;
    const int w = tid >> 5, lane = tid & 31;
    const int gp = lane >> 2, tgp = lane & 3;
    const int kh = blockIdx.x;
    const int r0 = blockIdx.y * 64;
    const int wn = w & 1;
    const int wr = (w >> 1) * 32, wc = wn * 32;
    const int rt0 = 2 * (w >> 1);

    const char* Df = (const char*)(g_DfH + (size_t)kh * 16 * 4096);
    const char* Af = (const char*)(g_AfH + (size_t)kh * 16 * 4096);

    // x staging map
    const int rowb = tid >> 4;              // 0..7 = g
    const int m = tid & 15;                 // col group: cols 4m..4m+3
    const int c4 = m * 4;
    const int ks4X = m >> 2, cphiX = (m >> 1) & 1, fX = fsw(ks4X);
    const int tg0 = (m & 1) * 2;

    const uint32_t sB0 = smem_u32(&sB[0][0]);
    const uint32_t sB1 = smem_u32(&sB[1][0]);

    // prologue (x kept fp32 in regs; convert at STS time, in the MMA shadow)
    float4 xa[8];
#pragma unroll
    for (int p = 0; p < 8; p++)
        xa[p] = *(const float4*)(x + (size_t)(r0 + rowb + p * 8) * 1024 + c4);
#pragma unroll
    for (int p = 0; p < 4; p++)
        CP_ASYNC16(sB0 + (tid + p * 128) * 16, Df + (tid + p * 128) * 16);
    CP_COMMIT();

    float acc[2][4][4];
#pragma unroll
    for (int mt = 0; mt < 2; mt++)
#pragma unroll
        for (int nt = 0; nt < 4; nt++)
#pragma unroll
            for (int i = 0; i < 4; i++) acc[mt][nt][i] = 0.f;

    // ---- Phase 1: 16 chunks of 64 depth ----
    for (int ci = 0; ci < 16; ci++) {
        const int b = ci & 1;
        // STS x chunk -> fp16 A-image
#pragma unroll
        for (int rt = 0; rt < 4; rt++) {
            float4 v0 = xa[2 * rt], v1 = xa[2 * rt + 1];
#pragma unroll
            for (int cs = 0; cs < 2; cs++) {
                int tg = tg0 + cs;
                int lane2 = (rowb * 4 + tg) ^ fX;
                int word = ((rt * 4 + ks4X) * 32 + lane2) * 4 + cphiX * 2;
                uint32_t lo = cs ? pack2h(v0.z, v0.w) : pack2h(v0.x, v0.y);
                uint32_t hi = cs ? pack2h(v1.z, v1.w) : pack2h(v1.x, v1.y);
                asm volatile("st.shared.v2.b32 [%0], {%1,%2};"
                             :: "r"(smem_u32(&sA[word])), "r"(lo), "r"(hi) : "memory");
            }
        }
        CP_WAIT0();
        __syncthreads();

        if (ci < 15) {
            int kc = (ci + 1) * 64;
#pragma unroll
            for (int p = 0; p < 8; p++)
                xa[p] = *(const float4*)(x + (size_t)(r0 + rowb + p * 8) * 1024 + kc + c4);
            const char* srcD = Df + (size_t)(ci + 1) * 8192;
            const uint32_t dst = b ? sB0 : sB1;
#pragma unroll
            for (int p = 0; p < 4; p++)
                CP_ASYNC16(dst + (tid + p * 128) * 16, srcD + (tid + p * 128) * 16);
            CP_COMMIT();
        }

        const uint32_t* Bp = sB[b];
#pragma unroll
        for (int ks4 = 0; ks4 < 4; ks4++) {
            int lsw = lane ^ fsw(ks4);
            uint32_t a0[4], a1[4];
            *(uint4*)a0 = *(const uint4*)&sA[((rt0 * 4 + ks4) * 32 + lsw) * 4];
            *(uint4*)a1 = *(const uint4*)&sA[(((rt0 + 1) * 4 + ks4) * 32 + lsw) * 4];
#pragma unroll
            for (int nt = 0; nt < 4; nt++) {
                uint32_t bb[2];
                *(uint2*)bb = *(const uint2*)&Bp[(((wn * 4 + nt) * 4 + ks4) * 32 + lane) * 2];
                mma16(acc[0][nt], a0, bb);
                mma16(acc[1][nt], a1, bb);
            }
        }
        __syncthreads();
    }

    // ---- spill u to sA (fp16 A-image) ----
#pragma unroll
    for (int mt = 0; mt < 2; mt++) {
        int rt = rt0 + mt;
#pragma unroll
        for (int nt = 0; nt < 4; nt++) {
            int ks4u = wn * 2 + (nt >> 1);
            int cphi = nt & 1;
            int lane2 = lane ^ fsw(ks4u);
            int word = ((rt * 4 + ks4u) * 32 + lane2) * 4 + cphi * 2;
            uint32_t lo = pack2h(acc[mt][nt][0], acc[mt][nt][1]);
            uint32_t hi = pack2h(acc[mt][nt][2], acc[mt][nt][3]);
            asm volatile("st.shared.v2.b32 [%0], {%1,%2};"
                         :: "r"(smem_u32(&sA[word])), "r"(lo), "r"(hi) : "memory");
        }
    }
#pragma unroll
    for (int p = 0; p < 4; p++)
        CP_ASYNC16(sB0 + (tid + p * 128) * 16, Af + (tid + p * 128) * 16);
    CP_COMMIT();
    __syncthreads();

    // u-fragments into registers
    uint32_t uf[2][4][4];
#pragma unroll
    for (int ks4 = 0; ks4 < 4; ks4++) {
        int lsw = lane ^ fsw(ks4);
        *(uint4*)uf[0][ks4] = *(const uint4*)&sA[((rt0 * 4 + ks4) * 32 + lsw) * 4];
        *(uint4*)uf[1][ks4] = *(const uint4*)&sA[(((rt0 + 1) * 4 + ks4) * 32 + lsw) * 4];
    }

    // ---- Phase 2: 16 etiles of 64 ----
    for (int et = 0; et < 16; et++) {
        const int b = et & 1;
        CP_WAIT0();
        __syncthreads();
        if (et < 15) {
            const char* srcA = Af + (size_t)(et + 1) * 8192;
            const uint32_t dst = b ? sB0 : sB1;
#pragma unroll
            for (int p = 0; p < 4; p++)
                CP_ASYNC16(dst + (tid + p * 128) * 16, srcA + (tid + p * 128) * 16);
            CP_COMMIT();
        }

        float o[2][4][4];
#pragma unroll
        for (int mt = 0; mt < 2; mt++)
#pragma unroll
            for (int nt = 0; nt < 4; nt++)
#pragma unroll
                for (int i = 0; i < 4; i++) o[mt][nt][i] = 0.f;

        const uint32_t* Bp = sB[b];
#pragma unroll
        for (int ks4 = 0; ks4 < 4; ks4++) {
#pragma unroll
            for (int nt = 0; nt < 4; nt++) {
                uint32_t bb[2];
                *(uint2*)bb = *(const uint2*)&Bp[(((wn * 4 + nt) * 4 + ks4) * 32 + lane) * 2];
                mma16(o[0][nt], uf[0][ks4], bb);
                mma16(o[1][nt], uf[1][ks4], bb);
            }
        }

#pragma unroll
        for (int mt = 0; mt < 2; mt++) {
            int row = r0 + wr + mt * 16 + gp;
#pragma unroll
            for (int nt = 0; nt < 4; nt++) {
                size_t col = (size_t)kh * 1024 + et * 64 + wc + nt * 8 + 2 * tgp;
                *(float2*)(out + (size_t)row * 3072 + col) =
                    make_float2(o[mt][nt][0], o[mt][nt][1]);
                *(float2*)(out + (size_t)(row + 8) * 3072 + col) =
                    make_float2(o[mt][nt][2], o[mt][nt][3]);
            }
        }
    }
}

extern "C" void kernel_launch(void* const* d_in, const int* in_sizes, int n_in,
                              void* d_out, int out_size) {
    (void)in_sizes; (void)n_in; (void)out_size;
    const float* x  = (const float*)d_in[0];
    const float* Ws = (const float*)d_in[1];
    const float* A  = (const float*)d_in[2];
    const float* B  = (const float*)d_in[3];
    float* out = (float*)d_out;

    cudaFuncSetAttribute(t1c_k, cudaFuncAttributeMaxDynamicSharedMemorySize, 69632);

    // fused_k is the 4th launch (ncu profiles launch #4)
    zero_k<<<48, 256>>>();
    t1c_k<<<dim3(6, 8, 3), 256, 69632>>>(B, Ws);
    d_k<<<dim3(160, 3), 256>>>(A);
    fused_k<<<dim3(3, 256), 128>>>(x, out);
}